// round 5
// baseline (speedup 1.0000x reference)
#include <cuda_runtime.h>
#include <math.h>

#define N_NODES 50000
#define N_EDGES 800000
#define HID 96
#define HEADS 4
#define HD 24
#define NEG_SLOPE 0.2f
#define FULL 0xffffffffu

// ---------------- scratch (no allocations allowed) ----------------
__device__ float g_feat[N_NODES * HID];
__device__ float g_h0[N_NODES * HID];
__device__ float g_h1[N_NODES * HID];
__device__ float g_el[N_NODES * HEADS];
__device__ float g_er[N_NODES * HEADS];
__device__ float g_w[N_EDGES * HEADS];    // fallback path only (deg > 32)
__device__ int   g_row_off[N_NODES + 1];
__device__ int   g_wptr[N_NODES];
__device__ int   g_csr_src[N_EDGES];
__device__ int   g_bsum[64];

// ---------------- CSR build ----------------
__global__ void zero_all_kernel(int* p, int n, float* out96) {
    int i = blockIdx.x * blockDim.x + threadIdx.x;
    if (i < n) p[i] = 0;
    if (i < 96) out96[i] = 0.f;
}

__global__ void count_kernel(const int* __restrict__ dst, int* __restrict__ counts) {
    int e = blockIdx.x * blockDim.x + threadIdx.x;
    if (e < N_EDGES) atomicAdd(&counts[dst[e]], 1);
}

__global__ void scan1_kernel(const int* __restrict__ in, int* __restrict__ out,
                             int* __restrict__ bsum, int n) {
    __shared__ int sh[1024];
    int i = blockIdx.x * 1024 + threadIdx.x;
    int v = (i < n) ? in[i] : 0;
    sh[threadIdx.x] = v;
    __syncthreads();
    for (int off = 1; off < 1024; off <<= 1) {
        int t = (threadIdx.x >= off) ? sh[threadIdx.x - off] : 0;
        __syncthreads();
        sh[threadIdx.x] += t;
        __syncthreads();
    }
    if (i < n) out[i] = sh[threadIdx.x] - v;
    if (threadIdx.x == 1023) bsum[blockIdx.x] = sh[1023];
}

__global__ void scan2_kernel(int* bsum, int nb) {
    __shared__ int sh[64];
    int t = threadIdx.x;
    int v = (t < nb) ? bsum[t] : 0;
    sh[t] = v;
    __syncthreads();
    for (int off = 1; off < 64; off <<= 1) {
        int x = (t >= off) ? sh[t - off] : 0;
        __syncthreads();
        sh[t] += x;
        __syncthreads();
    }
    if (t < nb) bsum[t] = sh[t] - v;
}

__global__ void scan3_kernel(int* __restrict__ row_off, int* __restrict__ wptr,
                             const int* __restrict__ bsum, int n, int total) {
    int i = blockIdx.x * 1024 + threadIdx.x;
    if (i < n) {
        int v = row_off[i] + bsum[i >> 10];
        row_off[i] = v;
        wptr[i] = v;
    }
    if (i == 0) row_off[n] = total;
}

__global__ void scatter_kernel(const int* __restrict__ src, const int* __restrict__ dst,
                               int* __restrict__ wptr, int* __restrict__ csr_src) {
    int e = blockIdx.x * blockDim.x + threadIdx.x;
    if (e < N_EDGES) {
        int p = atomicAdd(&wptr[dst[e]], 1);
        csr_src[p] = src[e];
    }
}

// ---------------- GEMM: C[n,96] = A[n,K] @ W[K,96] ----------------
// 2 CTAs/SM target: cap regs at 128 via launch_bounds minBlocks=2
__global__ __launch_bounds__(256, 2) void gemm_kernel(const float* __restrict__ A,
                                                      const float* __restrict__ W,
                                                      float* __restrict__ C, int n, int K) {
    __shared__ float As[128][33];
    __shared__ float Bs[32][96];
    int tid = threadIdx.x;
    int c = tid & 15;
    int r = tid >> 4;
    int row0 = blockIdx.x * 128;
    float acc[8][6] = {};

    for (int k0 = 0; k0 < K; k0 += 32) {
        #pragma unroll
        for (int t = 0; t < 4; t++) {
            int idx = tid + t * 256;
            int row = idx >> 3, kq = idx & 7;
            float4 v = make_float4(0.f, 0.f, 0.f, 0.f);
            if (row0 + row < n) v = *(const float4*)&A[(size_t)(row0 + row) * K + k0 + kq * 4];
            As[row][kq * 4 + 0] = v.x;
            As[row][kq * 4 + 1] = v.y;
            As[row][kq * 4 + 2] = v.z;
            As[row][kq * 4 + 3] = v.w;
        }
        #pragma unroll
        for (int t = 0; t < 12; t++) {
            int idx = tid + t * 256;
            int k = idx / 96, cc = idx - k * 96;
            Bs[k][cc] = W[(size_t)(k0 + k) * 96 + cc];
        }
        __syncthreads();
        #pragma unroll
        for (int kk = 0; kk < 32; kk++) {
            float b[6];
            #pragma unroll
            for (int j = 0; j < 6; j++) b[j] = Bs[kk][c + 16 * j];
            float a[8];
            #pragma unroll
            for (int i = 0; i < 8; i++) a[i] = As[r * 8 + i][kk];
            #pragma unroll
            for (int i = 0; i < 8; i++)
                #pragma unroll
                for (int j = 0; j < 6; j++)
                    acc[i][j] += a[i] * b[j];
        }
        __syncthreads();
    }
    #pragma unroll
    for (int i = 0; i < 8; i++) {
        int row = row0 + r * 8 + i;
        if (row < n) {
            #pragma unroll
            for (int j = 0; j < 6; j++)
                C[(size_t)row * 96 + c + 16 * j] = acc[i][j];
        }
    }
}

// ---------------- per-node attention coefficients ----------------
__global__ void attn_coef_kernel(const float* __restrict__ feat,
                                 const float* __restrict__ al, const float* __restrict__ ar,
                                 float* __restrict__ el, float* __restrict__ er) {
    int i = blockIdx.x * blockDim.x + threadIdx.x;
    if (i >= N_NODES * HEADS) return;
    int node = i >> 2, h = i & 3;
    const float* f = feat + (size_t)node * HID + h * HD;
    float sl = 0.f, sr = 0.f;
    #pragma unroll
    for (int d = 0; d < HD; d++) {
        float v = f[d];
        sl += v * al[h * HD + d];
        sr += v * ar[h * HD + d];
    }
    el[i] = sl;
    er[i] = sr;
}

// ---------------- aggregation: warp per node ----------------
// pass-2/epilogue layout: lane l (<24) owns cols [4l, 4l+4), head = l/6
__global__ void aggregate_kernel(const float* __restrict__ feat,
                                 const int* __restrict__ row_off,
                                 const int* __restrict__ csr_src,
                                 const float* __restrict__ el,
                                 const float* __restrict__ er,
                                 const float* __restrict__ bias,
                                 float* __restrict__ wbuf,
                                 float* __restrict__ out) {
    int warp = (blockIdx.x * blockDim.x + threadIdx.x) >> 5;
    int lane = threadIdx.x & 31;
    if (warp >= N_NODES) return;
    int node = warp;
    int beg = row_off[node], end = row_off[node + 1];
    int deg = end - beg;
    int myhead = lane / 6;                 // valid for lane < 24
    bool active = lane < 24;

    float ern[4];
    #pragma unroll
    for (int h = 0; h < 4; h++) ern[h] = er[node * 4 + h];

    float4 accv = make_float4(0.f, 0.f, 0.f, 0.f);
    float den[4] = {0.f, 0.f, 0.f, 0.f};

    if (deg <= 32) {
        // ---- fast path: everything register-resident ----
        int s = 0;
        float4 e = make_float4(-1e30f, -1e30f, -1e30f, -1e30f);
        if (lane < deg) {
            s = csr_src[beg + lane];
            float4 ev = *(const float4*)&el[s * 4];
            e.x = ev.x + ern[0]; e.x = e.x > 0.f ? e.x : NEG_SLOPE * e.x;
            e.y = ev.y + ern[1]; e.y = e.y > 0.f ? e.y : NEG_SLOPE * e.y;
            e.z = ev.z + ern[2]; e.z = e.z > 0.f ? e.z : NEG_SLOPE * e.z;
            e.w = ev.w + ern[3]; e.w = e.w > 0.f ? e.w : NEG_SLOPE * e.w;
        }
        float m0 = e.x, m1 = e.y, m2 = e.z, m3 = e.w;
        #pragma unroll
        for (int off = 16; off; off >>= 1) {
            m0 = fmaxf(m0, __shfl_xor_sync(FULL, m0, off));
            m1 = fmaxf(m1, __shfl_xor_sync(FULL, m1, off));
            m2 = fmaxf(m2, __shfl_xor_sync(FULL, m2, off));
            m3 = fmaxf(m3, __shfl_xor_sync(FULL, m3, off));
        }
        float4 w = make_float4(0.f, 0.f, 0.f, 0.f);
        if (lane < deg) {
            w.x = __expf(e.x - m0);
            w.y = __expf(e.y - m1);
            w.z = __expf(e.z - m2);
            w.w = __expf(e.w - m3);
        }
        den[0] = w.x; den[1] = w.y; den[2] = w.z; den[3] = w.w;
        #pragma unroll
        for (int off = 16; off; off >>= 1) {
            den[0] += __shfl_xor_sync(FULL, den[0], off);
            den[1] += __shfl_xor_sync(FULL, den[1], off);
            den[2] += __shfl_xor_sync(FULL, den[2], off);
            den[3] += __shfl_xor_sync(FULL, den[3], off);
        }
        #pragma unroll 4
        for (int i = 0; i < deg; i++) {
            int ss   = __shfl_sync(FULL, s, i);
            float wx = __shfl_sync(FULL, w.x, i);
            float wy = __shfl_sync(FULL, w.y, i);
            float wz = __shfl_sync(FULL, w.z, i);
            float ww = __shfl_sync(FULL, w.w, i);
            float wv = myhead == 0 ? wx : (myhead == 1 ? wy : (myhead == 2 ? wz : ww));
            if (active) {
                float4 f = *(const float4*)&feat[(size_t)ss * 96 + lane * 4];
                accv.x += wv * f.x;
                accv.y += wv * f.y;
                accv.z += wv * f.z;
                accv.w += wv * f.w;
            }
        }
    } else {
        // ---- fallback path (rare): via wbuf ----
        float m[4] = {-1e30f, -1e30f, -1e30f, -1e30f};
        for (int i = beg + lane; i < end; i += 32) {
            int s = csr_src[i];
            float4 ev = *(const float4*)&el[s * 4];
            float4 e;
            e.x = ev.x + ern[0]; e.x = e.x > 0.f ? e.x : NEG_SLOPE * e.x; m[0] = fmaxf(m[0], e.x);
            e.y = ev.y + ern[1]; e.y = e.y > 0.f ? e.y : NEG_SLOPE * e.y; m[1] = fmaxf(m[1], e.y);
            e.z = ev.z + ern[2]; e.z = e.z > 0.f ? e.z : NEG_SLOPE * e.z; m[2] = fmaxf(m[2], e.z);
            e.w = ev.w + ern[3]; e.w = e.w > 0.f ? e.w : NEG_SLOPE * e.w; m[3] = fmaxf(m[3], e.w);
            *(float4*)&wbuf[(size_t)i * 4] = e;
        }
        #pragma unroll
        for (int off = 16; off; off >>= 1)
            #pragma unroll
            for (int h = 0; h < 4; h++)
                m[h] = fmaxf(m[h], __shfl_xor_sync(FULL, m[h], off));

        for (int i = beg + lane; i < end; i += 32) {
            float4 e = *(const float4*)&wbuf[(size_t)i * 4];
            float4 w;
            w.x = __expf(e.x - m[0]); den[0] += w.x;
            w.y = __expf(e.y - m[1]); den[1] += w.y;
            w.z = __expf(e.z - m[2]); den[2] += w.z;
            w.w = __expf(e.w - m[3]); den[3] += w.w;
            *(float4*)&wbuf[(size_t)i * 4] = w;
        }
        #pragma unroll
        for (int off = 16; off; off >>= 1)
            #pragma unroll
            for (int h = 0; h < 4; h++)
                den[h] += __shfl_xor_sync(FULL, den[h], off);

        #pragma unroll 4
        for (int i = beg; i < end; i++) {
            int ss = csr_src[i];                              // broadcast load
            float4 w = *(const float4*)&wbuf[(size_t)i * 4];  // broadcast load
            float wv = myhead == 0 ? w.x : (myhead == 1 ? w.y : (myhead == 2 ? w.z : w.w));
            if (active) {
                float4 f = *(const float4*)&feat[(size_t)ss * 96 + lane * 4];
                accv.x += wv * f.x;
                accv.y += wv * f.y;
                accv.z += wv * f.z;
                accv.w += wv * f.w;
            }
        }
    }

    // epilogue: normalize + bias + ELU (lanes 0..23, 4 cols each)
    if (active) {
        float inv = (deg > 0)
            ? 1.f / (myhead == 0 ? den[0] : (myhead == 1 ? den[1] : (myhead == 2 ? den[2] : den[3])))
            : 0.f;
        float4 bv = *(const float4*)&bias[lane * 4];
        float v0 = accv.x * inv + bv.x;
        float v1 = accv.y * inv + bv.y;
        float v2 = accv.z * inv + bv.z;
        float v3 = accv.w * inv + bv.w;
        v0 = v0 > 0.f ? v0 : expm1f(v0);
        v1 = v1 > 0.f ? v1 : expm1f(v1);
        v2 = v2 > 0.f ? v2 : expm1f(v2);
        v3 = v3 > 0.f ? v3 : expm1f(v3);
        *(float4*)&out[(size_t)node * 96 + lane * 4] = make_float4(v0, v1, v2, v3);
    }
}

// ---------------- final mean pool ----------------
__global__ void mean_kernel(const float* __restrict__ h, float* __restrict__ out) {
    int c = threadIdx.x;
    int b = blockIdx.x;
    float s = 0.f;
    for (int r = b; r < N_NODES; r += gridDim.x) s += h[(size_t)r * 96 + c];
    atomicAdd(&out[c], s * (1.f / N_NODES));
}

// ---------------- launch ----------------
extern "C" void kernel_launch(void* const* d_in, const int* in_sizes, int n_in,
                              void* d_out, int out_size) {
    const float* feats = (const float*)d_in[0];
    const int*   src   = (const int*)d_in[1];
    const int*   dst   = (const int*)d_in[2];
    const float* W[3]  = {(const float*)d_in[3],  (const float*)d_in[7],  (const float*)d_in[11]};
    const float* al[3] = {(const float*)d_in[4],  (const float*)d_in[8],  (const float*)d_in[12]};
    const float* ar[3] = {(const float*)d_in[5],  (const float*)d_in[9],  (const float*)d_in[13]};
    const float* bb[3] = {(const float*)d_in[6],  (const float*)d_in[10], (const float*)d_in[14]};

    float *feat, *h0, *h1, *el, *er, *wb;
    int *row_off, *wptr, *csr, *bsum;
    cudaGetSymbolAddress((void**)&feat,    g_feat);
    cudaGetSymbolAddress((void**)&h0,      g_h0);
    cudaGetSymbolAddress((void**)&h1,      g_h1);
    cudaGetSymbolAddress((void**)&el,      g_el);
    cudaGetSymbolAddress((void**)&er,      g_er);
    cudaGetSymbolAddress((void**)&wb,      g_w);
    cudaGetSymbolAddress((void**)&row_off, g_row_off);
    cudaGetSymbolAddress((void**)&wptr,    g_wptr);
    cudaGetSymbolAddress((void**)&csr,     g_csr_src);
    cudaGetSymbolAddress((void**)&bsum,    g_bsum);

    const int SB = 49;  // ceil(50000/1024)
    int gemm_grid = (N_NODES + 127) / 128;

    // idx 0-2: CSR build start
    zero_all_kernel<<<(N_NODES + 255) / 256, 256>>>(wptr, N_NODES, (float*)d_out);
    count_kernel<<<(N_EDGES + 255) / 256, 256>>>(dst, wptr);
    scan1_kernel<<<SB, 1024>>>(wptr, row_off, bsum, N_NODES);
    // idx 3: gemm layer 1 — ncu sampling slot
    gemm_kernel<<<gemm_grid, 256>>>(feats, W[0], feat, N_NODES, 128);
    // idx 4-6: finish CSR
    scan2_kernel<<<1, 64>>>(bsum, SB);
    scan3_kernel<<<SB, 1024>>>(row_off, wptr, bsum, N_NODES, N_EDGES);
    scatter_kernel<<<(N_EDGES + 255) / 256, 256>>>(src, dst, wptr, csr);

    // layer 1 rest
    attn_coef_kernel<<<(N_NODES * HEADS + 255) / 256, 256>>>(feat, al[0], ar[0], el, er);
    aggregate_kernel<<<(N_NODES * 32 + 255) / 256, 256>>>(feat, row_off, csr, el, er,
                                                          bb[0], wb, h0);
    // layers 2, 3
    const float* hin = h0;
    float* houts[3] = {h0, h1, h0};
    for (int l = 1; l < 3; l++) {
        gemm_kernel<<<gemm_grid, 256>>>(hin, W[l], feat, N_NODES, 96);
        attn_coef_kernel<<<(N_NODES * HEADS + 255) / 256, 256>>>(feat, al[l], ar[l], el, er);
        aggregate_kernel<<<(N_NODES * 32 + 255) / 256, 256>>>(feat, row_off, csr, el, er,
                                                              bb[l], wb, houts[l]);
        hin = houts[l];
    }

    mean_kernel<<<64, 96>>>(hin, (float*)d_out);
}

// round 6
// speedup vs baseline: 1.5761x; 1.5761x over previous
#include <cuda_runtime.h>
#include <math.h>

#define N_NODES 50000
#define N_EDGES 800000
#define HID 96
#define HEADS 4
#define HD 24
#define NEG_SLOPE 0.2f
#define FULL 0xffffffffu

// ---------------- scratch (no allocations allowed) ----------------
__device__ float g_feat[N_NODES * HID];
__device__ float g_h0[N_NODES * HID];
__device__ float g_h1[N_NODES * HID];
__device__ float g_el[N_NODES * HEADS];
__device__ float g_er[N_NODES * HEADS];
__device__ float g_w[N_EDGES * HEADS];    // fallback path only (deg > 32)
__device__ int   g_row_off[N_NODES + 1];
__device__ int   g_wptr[N_NODES];
__device__ int   g_csr_src[N_EDGES];
__device__ int   g_bsum[64];

// ---------------- CSR build ----------------
__global__ void zero_all_kernel(int* p, int n, float* out96) {
    int i = blockIdx.x * blockDim.x + threadIdx.x;
    if (i < n) p[i] = 0;
    if (i < 96) out96[i] = 0.f;
}

__global__ void count_kernel(const int* __restrict__ dst, int* __restrict__ counts) {
    int e = blockIdx.x * blockDim.x + threadIdx.x;
    if (e < N_EDGES) atomicAdd(&counts[dst[e]], 1);
}

__global__ void scan1_kernel(const int* __restrict__ in, int* __restrict__ out,
                             int* __restrict__ bsum, int n) {
    __shared__ int sh[1024];
    int i = blockIdx.x * 1024 + threadIdx.x;
    int v = (i < n) ? in[i] : 0;
    sh[threadIdx.x] = v;
    __syncthreads();
    for (int off = 1; off < 1024; off <<= 1) {
        int t = (threadIdx.x >= off) ? sh[threadIdx.x - off] : 0;
        __syncthreads();
        sh[threadIdx.x] += t;
        __syncthreads();
    }
    if (i < n) out[i] = sh[threadIdx.x] - v;
    if (threadIdx.x == 1023) bsum[blockIdx.x] = sh[1023];
}

__global__ void scan2_kernel(int* bsum, int nb) {
    __shared__ int sh[64];
    int t = threadIdx.x;
    int v = (t < nb) ? bsum[t] : 0;
    sh[t] = v;
    __syncthreads();
    for (int off = 1; off < 64; off <<= 1) {
        int x = (t >= off) ? sh[t - off] : 0;
        __syncthreads();
        sh[t] += x;
        __syncthreads();
    }
    if (t < nb) bsum[t] = sh[t] - v;
}

__global__ void scan3_kernel(int* __restrict__ row_off, int* __restrict__ wptr,
                             const int* __restrict__ bsum, int n, int total) {
    int i = blockIdx.x * 1024 + threadIdx.x;
    if (i < n) {
        int v = row_off[i] + bsum[i >> 10];
        row_off[i] = v;
        wptr[i] = v;
    }
    if (i == 0) row_off[n] = total;
}

__global__ void scatter_kernel(const int* __restrict__ src, const int* __restrict__ dst,
                               int* __restrict__ wptr, int* __restrict__ csr_src) {
    int e = blockIdx.x * blockDim.x + threadIdx.x;
    if (e < N_EDGES) {
        int p = atomicAdd(&wptr[dst[e]], 1);
        csr_src[p] = src[e];
    }
}

// ---------------- GEMM: C[n,96] = A[n,K] @ W[K,96] ----------------
// block tile 128x96, 512 threads, micro-tile 4x6 (24 acc) -> ~60-80 regs, no spills,
// 16 warps/block and 2 blocks/SM (smem 28.5KB) to hide latency.
__global__ __launch_bounds__(512) void gemm_kernel(const float* __restrict__ A,
                                                   const float* __restrict__ W,
                                                   float* __restrict__ C, int n, int K) {
    __shared__ float As[128][33];
    __shared__ float Bs[32][96];
    int tid = threadIdx.x;
    int c = tid & 15;       // cols c + 16j, j=0..5
    int r = tid >> 4;       // row group 0..31, rows r*4 .. r*4+3
    int row0 = blockIdx.x * 128;
    float acc[4][6] = {};

    for (int k0 = 0; k0 < K; k0 += 32) {
        // A tile: 128x32 = 1024 float4, 2 per thread
        #pragma unroll
        for (int t = 0; t < 2; t++) {
            int idx = tid + t * 512;
            int row = idx >> 3, kq = idx & 7;
            float4 v = make_float4(0.f, 0.f, 0.f, 0.f);
            if (row0 + row < n) v = *(const float4*)&A[(size_t)(row0 + row) * K + k0 + kq * 4];
            As[row][kq * 4 + 0] = v.x;
            As[row][kq * 4 + 1] = v.y;
            As[row][kq * 4 + 2] = v.z;
            As[row][kq * 4 + 3] = v.w;
        }
        // B tile: 32x96 = 3072 floats, 6 per thread
        #pragma unroll
        for (int t = 0; t < 6; t++) {
            int idx = tid + t * 512;
            int k = idx / 96, cc = idx - k * 96;
            Bs[k][cc] = W[(size_t)(k0 + k) * 96 + cc];
        }
        __syncthreads();
        #pragma unroll
        for (int kk = 0; kk < 32; kk++) {
            float b[6];
            #pragma unroll
            for (int j = 0; j < 6; j++) b[j] = Bs[kk][c + 16 * j];
            float a[4];
            #pragma unroll
            for (int i = 0; i < 4; i++) a[i] = As[r * 4 + i][kk];
            #pragma unroll
            for (int i = 0; i < 4; i++)
                #pragma unroll
                for (int j = 0; j < 6; j++)
                    acc[i][j] += a[i] * b[j];
        }
        __syncthreads();
    }
    #pragma unroll
    for (int i = 0; i < 4; i++) {
        int row = row0 + r * 4 + i;
        if (row < n) {
            #pragma unroll
            for (int j = 0; j < 6; j++)
                C[(size_t)row * 96 + c + 16 * j] = acc[i][j];
        }
    }
}

// ---------------- per-node attention coefficients ----------------
__global__ void attn_coef_kernel(const float* __restrict__ feat,
                                 const float* __restrict__ al, const float* __restrict__ ar,
                                 float* __restrict__ el, float* __restrict__ er) {
    int i = blockIdx.x * blockDim.x + threadIdx.x;
    if (i >= N_NODES * HEADS) return;
    int node = i >> 2, h = i & 3;
    const float* f = feat + (size_t)node * HID + h * HD;
    float sl = 0.f, sr = 0.f;
    #pragma unroll
    for (int d = 0; d < HD; d++) {
        float v = f[d];
        sl += v * al[h * HD + d];
        sr += v * ar[h * HD + d];
    }
    el[i] = sl;
    er[i] = sr;
}

// ---------------- aggregation: warp per node (R4-proven version) ----------------
__global__ void aggregate_kernel(const float* __restrict__ feat,
                                 const int* __restrict__ row_off,
                                 const int* __restrict__ csr_src,
                                 const float* __restrict__ el,
                                 const float* __restrict__ er,
                                 const float* __restrict__ bias,
                                 float* __restrict__ wbuf,
                                 float* __restrict__ out) {
    int warp = (blockIdx.x * blockDim.x + threadIdx.x) >> 5;
    int lane = threadIdx.x & 31;
    if (warp >= N_NODES) return;
    int node = warp;
    int beg = row_off[node], end = row_off[node + 1];
    int deg = end - beg;

    float ern[4];
    #pragma unroll
    for (int h = 0; h < 4; h++) ern[h] = er[node * 4 + h];

    float acc0 = 0.f, acc1 = 0.f, acc2 = 0.f;
    float den[4] = {0.f, 0.f, 0.f, 0.f};

    if (deg <= 32) {
        // ---- fast path: everything register-resident, shfl broadcast ----
        int s = -1;
        float4 e = make_float4(-1e30f, -1e30f, -1e30f, -1e30f);
        if (lane < deg) {
            s = csr_src[beg + lane];
            float4 ev = *(const float4*)&el[s * 4];
            e.x = ev.x + ern[0]; e.x = e.x > 0.f ? e.x : NEG_SLOPE * e.x;
            e.y = ev.y + ern[1]; e.y = e.y > 0.f ? e.y : NEG_SLOPE * e.y;
            e.z = ev.z + ern[2]; e.z = e.z > 0.f ? e.z : NEG_SLOPE * e.z;
            e.w = ev.w + ern[3]; e.w = e.w > 0.f ? e.w : NEG_SLOPE * e.w;
        }
        float m0 = e.x, m1 = e.y, m2 = e.z, m3 = e.w;
        #pragma unroll
        for (int off = 16; off; off >>= 1) {
            m0 = fmaxf(m0, __shfl_xor_sync(FULL, m0, off));
            m1 = fmaxf(m1, __shfl_xor_sync(FULL, m1, off));
            m2 = fmaxf(m2, __shfl_xor_sync(FULL, m2, off));
            m3 = fmaxf(m3, __shfl_xor_sync(FULL, m3, off));
        }
        float4 w = make_float4(0.f, 0.f, 0.f, 0.f);
        if (lane < deg) {
            w.x = __expf(e.x - m0);
            w.y = __expf(e.y - m1);
            w.z = __expf(e.z - m2);
            w.w = __expf(e.w - m3);
        }
        den[0] = w.x; den[1] = w.y; den[2] = w.z; den[3] = w.w;
        #pragma unroll
        for (int off = 16; off; off >>= 1) {
            den[0] += __shfl_xor_sync(FULL, den[0], off);
            den[1] += __shfl_xor_sync(FULL, den[1], off);
            den[2] += __shfl_xor_sync(FULL, den[2], off);
            den[3] += __shfl_xor_sync(FULL, den[3], off);
        }
        for (int i = 0; i < deg; i++) {
            int ss   = __shfl_sync(FULL, s, i);
            float wx = __shfl_sync(FULL, w.x, i);
            float wy = __shfl_sync(FULL, w.y, i);
            float wz = __shfl_sync(FULL, w.z, i);
            float ww = __shfl_sync(FULL, w.w, i);
            const float* fs = feat + (size_t)ss * 96;
            float wA = (lane < 24) ? wx : wy;
            float wB = (lane < 16) ? wy : wz;
            float wC = (lane < 8)  ? wz : ww;
            acc0 += wA * fs[lane];
            acc1 += wB * fs[lane + 32];
            acc2 += wC * fs[lane + 64];
        }
    } else {
        // ---- fallback path (rare): via wbuf ----
        float m[4] = {-1e30f, -1e30f, -1e30f, -1e30f};
        for (int i = beg + lane; i < end; i += 32) {
            int s = csr_src[i];
            float4 ev = *(const float4*)&el[s * 4];
            float4 e;
            e.x = ev.x + ern[0]; e.x = e.x > 0.f ? e.x : NEG_SLOPE * e.x; m[0] = fmaxf(m[0], e.x);
            e.y = ev.y + ern[1]; e.y = e.y > 0.f ? e.y : NEG_SLOPE * e.y; m[1] = fmaxf(m[1], e.y);
            e.z = ev.z + ern[2]; e.z = e.z > 0.f ? e.z : NEG_SLOPE * e.z; m[2] = fmaxf(m[2], e.z);
            e.w = ev.w + ern[3]; e.w = e.w > 0.f ? e.w : NEG_SLOPE * e.w; m[3] = fmaxf(m[3], e.w);
            *(float4*)&wbuf[(size_t)i * 4] = e;
        }
        #pragma unroll
        for (int off = 16; off; off >>= 1)
            #pragma unroll
            for (int h = 0; h < 4; h++)
                m[h] = fmaxf(m[h], __shfl_xor_sync(FULL, m[h], off));

        for (int i = beg + lane; i < end; i += 32) {
            float4 e = *(const float4*)&wbuf[(size_t)i * 4];
            float4 w;
            w.x = __expf(e.x - m[0]); den[0] += w.x;
            w.y = __expf(e.y - m[1]); den[1] += w.y;
            w.z = __expf(e.z - m[2]); den[2] += w.z;
            w.w = __expf(e.w - m[3]); den[3] += w.w;
            *(float4*)&wbuf[(size_t)i * 4] = w;
        }
        #pragma unroll
        for (int off = 16; off; off >>= 1)
            #pragma unroll
            for (int h = 0; h < 4; h++)
                den[h] += __shfl_xor_sync(FULL, den[h], off);

        for (int i = beg; i < end; i++) {
            int s = csr_src[i];
            float4 w = *(const float4*)&wbuf[(size_t)i * 4];
            const float* fs = feat + (size_t)s * 96;
            float wA = (lane < 24) ? w.x : w.y;
            float wB = (lane < 16) ? w.y : w.z;
            float wC = (lane < 8)  ? w.z : w.w;
            acc0 += wA * fs[lane];
            acc1 += wB * fs[lane + 32];
            acc2 += wC * fs[lane + 64];
        }
    }

    float inv[4];
    #pragma unroll
    for (int h = 0; h < 4; h++) inv[h] = (deg > 0) ? (1.f / den[h]) : 0.f;
    float iA = (lane < 24) ? inv[0] : inv[1];
    float iB = (lane < 16) ? inv[1] : inv[2];
    float iC = (lane < 8)  ? inv[2] : inv[3];

    float v0 = acc0 * iA + bias[lane];
    float v1 = acc1 * iB + bias[lane + 32];
    float v2 = acc2 * iC + bias[lane + 64];
    v0 = v0 > 0.f ? v0 : expm1f(v0);
    v1 = v1 > 0.f ? v1 : expm1f(v1);
    v2 = v2 > 0.f ? v2 : expm1f(v2);
    out[(size_t)node * 96 + lane]      = v0;
    out[(size_t)node * 96 + lane + 32] = v1;
    out[(size_t)node * 96 + lane + 64] = v2;
}

// ---------------- final mean pool ----------------
__global__ void mean_kernel(const float* __restrict__ h, float* __restrict__ out) {
    int c = threadIdx.x;
    int b = blockIdx.x;
    float s = 0.f;
    for (int r = b; r < N_NODES; r += gridDim.x) s += h[(size_t)r * 96 + c];
    atomicAdd(&out[c], s * (1.f / N_NODES));
}

// ---------------- launch ----------------
extern "C" void kernel_launch(void* const* d_in, const int* in_sizes, int n_in,
                              void* d_out, int out_size) {
    const float* feats = (const float*)d_in[0];
    const int*   src   = (const int*)d_in[1];
    const int*   dst   = (const int*)d_in[2];
    const float* W[3]  = {(const float*)d_in[3],  (const float*)d_in[7],  (const float*)d_in[11]};
    const float* al[3] = {(const float*)d_in[4],  (const float*)d_in[8],  (const float*)d_in[12]};
    const float* ar[3] = {(const float*)d_in[5],  (const float*)d_in[9],  (const float*)d_in[13]};
    const float* bb[3] = {(const float*)d_in[6],  (const float*)d_in[10], (const float*)d_in[14]};

    float *feat, *h0, *h1, *el, *er, *wb;
    int *row_off, *wptr, *csr, *bsum;
    cudaGetSymbolAddress((void**)&feat,    g_feat);
    cudaGetSymbolAddress((void**)&h0,      g_h0);
    cudaGetSymbolAddress((void**)&h1,      g_h1);
    cudaGetSymbolAddress((void**)&el,      g_el);
    cudaGetSymbolAddress((void**)&er,      g_er);
    cudaGetSymbolAddress((void**)&wb,      g_w);
    cudaGetSymbolAddress((void**)&row_off, g_row_off);
    cudaGetSymbolAddress((void**)&wptr,    g_wptr);
    cudaGetSymbolAddress((void**)&csr,     g_csr_src);
    cudaGetSymbolAddress((void**)&bsum,    g_bsum);

    const int SB = 49;  // ceil(50000/1024)
    int gemm_grid = (N_NODES + 127) / 128;

    // idx 0-2: CSR build start
    zero_all_kernel<<<(N_NODES + 255) / 256, 256>>>(wptr, N_NODES, (float*)d_out);
    count_kernel<<<(N_EDGES + 255) / 256, 256>>>(dst, wptr);
    scan1_kernel<<<SB, 1024>>>(wptr, row_off, bsum, N_NODES);
    // idx 3: gemm layer 1 — ncu sampling slot
    gemm_kernel<<<gemm_grid, 512>>>(feats, W[0], feat, N_NODES, 128);
    // idx 4-6: finish CSR
    scan2_kernel<<<1, 64>>>(bsum, SB);
    scan3_kernel<<<SB, 1024>>>(row_off, wptr, bsum, N_NODES, N_EDGES);
    scatter_kernel<<<(N_EDGES + 255) / 256, 256>>>(src, dst, wptr, csr);

    // layer 1 rest
    attn_coef_kernel<<<(N_NODES * HEADS + 255) / 256, 256>>>(feat, al[0], ar[0], el, er);
    aggregate_kernel<<<(N_NODES * 32 + 255) / 256, 256>>>(feat, row_off, csr, el, er,
                                                          bb[0], wb, h0);
    // layers 2, 3
    const float* hin = h0;
    float* houts[3] = {h0, h1, h0};
    for (int l = 1; l < 3; l++) {
        gemm_kernel<<<gemm_grid, 512>>>(hin, W[l], feat, N_NODES, 96);
        attn_coef_kernel<<<(N_NODES * HEADS + 255) / 256, 256>>>(feat, al[l], ar[l], el, er);
        aggregate_kernel<<<(N_NODES * 32 + 255) / 256, 256>>>(feat, row_off, csr, el, er,
                                                              bb[l], wb, houts[l]);
        hin = houts[l];
    }

    mean_kernel<<<64, 96>>>(hin, (float*)d_out);
}